// round 15
// baseline (speedup 1.0000x reference)
#include <cuda_runtime.h>
#include <cuda_bf16.h>
#include <cuda_fp16.h>
#include <mma.h>
#include <cstdint>

using namespace nvcuda;

#define VV 32000
#define HH 1024
#define BB 32
#define SS 64
#define H3 3072
#define MM (SS*BB)   // 2048

#if !defined(__CUDA_ARCH__) || defined(__CUDA_ARCH_FEAT_SM103_ALL)
#define TC_OK 1
#else
#define TC_OK 0
#endif

// ---------------- scratch ----------------
__device__ __nv_bfloat16 g_Xb[(size_t)MM*HH];
__device__ __nv_bfloat16 g_Xlo[(size_t)MM*HH];
__device__ __nv_bfloat16 g_Wihb[(size_t)H3*HH];
__device__ __nv_bfloat16 g_Wihlo[(size_t)H3*HH];
__device__ __half        g_Whh16[(size_t)H3*HH];
__device__ __nv_bfloat16 g_Woutb[(size_t)VV*HH];
__device__ __nv_bfloat16 g_HSb[(size_t)MM*HH];
__device__ float g_GI[(size_t)MM*H3];
__device__ float g_hf[2][BB*HH];
__device__ __half g_hh16[2][BB*HH];
__device__ float g_lsm_m[MM][256];   // per-(row, 128-col block) max (250 used)
__device__ float g_lsm_s[MM][256];   // per-(row, 128-col block) sumexp
__device__ int g_bar;

// ---------------- cp.async helpers ----------------
__device__ __forceinline__ uint32_t smem_u32(const void* p){
    return (uint32_t)__cvta_generic_to_shared(p);
}
__device__ __forceinline__ void cp16(void* dst, const void* src){
    asm volatile("cp.async.cg.shared.global [%0], [%1], 16;" :: "r"(smem_u32(dst)), "l"(src));
}
__device__ __forceinline__ void cp16a(uint32_t dst, const void* src){
    asm volatile("cp.async.cg.shared.global [%0], [%1], 16;" :: "r"(dst), "l"(src));
}
__device__ __forceinline__ void cp_commit(){ asm volatile("cp.async.commit_group;"); }
template<int N> __device__ __forceinline__ void cp_wait(){ asm volatile("cp.async.wait_group %0;" :: "n"(N)); }

#define SWZ128(off) ((off) ^ (((off) >> 3) & 0x70))

#if TC_OK
// ---------------- tcgen05 helpers ----------------
static __device__ __forceinline__ uint64_t make_desc(uint32_t addr){
    const uint64_t base = (2ULL<<61) | (1ULL<<46) | (64ULL<<32) | (1ULL<<16); // SW128, v1, SBO=64, LBO=1
    return base | (uint64_t)((addr >> 4) & 0x3FFF);
}
__device__ __forceinline__ void mma_f16_ss(uint32_t d, uint64_t ad, uint64_t bd, uint32_t idesc, uint32_t en){
    asm volatile(
        "{\n\t.reg .pred p;\n\t"
        "setp.ne.u32 p, %5, 0;\n\t"
        "tcgen05.mma.cta_group::1.kind::f16 [%0], %1, %2, %3, {%4, %4, %4, %4}, p;\n\t}"
        :: "r"(d), "l"(ad), "l"(bd), "r"(idesc), "r"(0u), "r"(en) : "memory");
}
__device__ __forceinline__ void tc_commit(uint32_t mbar){
    asm volatile("tcgen05.commit.cta_group::1.mbarrier::arrive::one.shared::cluster.b64 [%0];" :: "r"(mbar) : "memory");
}
__device__ __forceinline__ void mbar_init(uint32_t mbar, uint32_t cnt){
    asm volatile("mbarrier.init.shared.b64 [%0], %1;" :: "r"(mbar), "r"(cnt) : "memory");
}
__device__ __forceinline__ void mbar_wait(uint32_t mbar, uint32_t parity){
    asm volatile(
        "{\n\t.reg .pred P1;\n\t"
        "W_%=:\n\t"
        "mbarrier.try_wait.parity.acquire.cta.shared::cta.b64 P1, [%0], %1, 0x989680;\n\t"
        "@!P1 bra.uni W_%=;\n\t}"
        :: "r"(mbar), "r"(parity) : "memory");
}
#define TC_LD_X32(r, a) \
    asm volatile( \
        "tcgen05.ld.sync.aligned.32x32b.x32.b32 " \
        "{%0, %1, %2, %3, %4, %5, %6, %7, " \
        " %8, %9, %10, %11, %12, %13, %14, %15, " \
        " %16, %17, %18, %19, %20, %21, %22, %23, " \
        " %24, %25, %26, %27, %28, %29, %30, %31}, [%32];" \
        : "=r"((r)[0]),  "=r"((r)[1]),  "=r"((r)[2]),  "=r"((r)[3]), \
          "=r"((r)[4]),  "=r"((r)[5]),  "=r"((r)[6]),  "=r"((r)[7]), \
          "=r"((r)[8]),  "=r"((r)[9]),  "=r"((r)[10]), "=r"((r)[11]), \
          "=r"((r)[12]), "=r"((r)[13]), "=r"((r)[14]), "=r"((r)[15]), \
          "=r"((r)[16]), "=r"((r)[17]), "=r"((r)[18]), "=r"((r)[19]), \
          "=r"((r)[20]), "=r"((r)[21]), "=r"((r)[22]), "=r"((r)[23]), \
          "=r"((r)[24]), "=r"((r)[25]), "=r"((r)[26]), "=r"((r)[27]), \
          "=r"((r)[28]), "=r"((r)[29]), "=r"((r)[30]), "=r"((r)[31]) \
        : "r"(a))
#define TC_WAIT_LD()  asm volatile("tcgen05.wait::ld.sync.aligned;" ::: "memory")
#define TC_FENCE_AFTER() asm volatile("tcgen05.fence::after_thread_sync;" ::: "memory")
#endif // TC_OK

// ---------------- fp32 -> bf16 ----------------
__global__ void f2b_kernel(const float* __restrict__ in, __nv_bfloat16* __restrict__ out, size_t n4)
{
    size_t i = (size_t)blockIdx.x * blockDim.x + threadIdx.x;
    if (i >= n4) return;
    float4 v = reinterpret_cast<const float4*>(in)[i];
    reinterpret_cast<__nv_bfloat162*>(out)[2*i]   = __floats2bfloat162_rn(v.x, v.y);
    reinterpret_cast<__nv_bfloat162*>(out)[2*i+1] = __floats2bfloat162_rn(v.z, v.w);
}

// ---------------- weight prep: W_ih -> bf16 hi/lo, W_hh -> fp16 ----------------
__global__ void wprep_kernel(const float* __restrict__ wih,
                             __nv_bfloat16* __restrict__ hi, __nv_bfloat16* __restrict__ lo,
                             const float* __restrict__ whh, __half* __restrict__ w16,
                             size_t n4each)
{
    size_t i = (size_t)blockIdx.x * blockDim.x + threadIdx.x;
    if (i >= 2*n4each) return;
    if (i >= n4each){
        i -= n4each;
        float4 v = reinterpret_cast<const float4*>(whh)[i];
        reinterpret_cast<__half2*>(w16)[2*i]   = __floats2half2_rn(v.x, v.y);
        reinterpret_cast<__half2*>(w16)[2*i+1] = __floats2half2_rn(v.z, v.w);
        return;
    }
    float4 v = reinterpret_cast<const float4*>(wih)[i];
    float a[4] = {v.x, v.y, v.z, v.w};
    __nv_bfloat16 h[4], l[4];
    #pragma unroll
    for (int k=0;k<4;k++) {
        h[k] = __float2bfloat16(a[k]);
        l[k] = __float2bfloat16(a[k] - __bfloat162float(h[k]));
    }
    reinterpret_cast<__nv_bfloat162*>(hi)[2*i]   = __nv_bfloat162{h[0],h[1]};
    reinterpret_cast<__nv_bfloat162*>(hi)[2*i+1] = __nv_bfloat162{h[2],h[3]};
    reinterpret_cast<__nv_bfloat162*>(lo)[2*i]   = __nv_bfloat162{l[0],l[1]};
    reinterpret_cast<__nv_bfloat162*>(lo)[2*i+1] = __nv_bfloat162{l[2],l[3]};
}

// ---------------- embedding+relu->bf16 hi/lo + h0 init ----------------
__global__ void embed_init_kernel(const float* __restrict__ emb, const int* __restrict__ tgt,
                                  const int* __restrict__ bos, const float* __restrict__ enc)
{
    int row = blockIdx.x;
    int t = row >> 5, b = row & 31;
    int tok = (t == 0) ? bos[0] : tgt[b*SS + t - 1];
    const float* e = &emb[(size_t)tok * HH];
    for (int i = threadIdx.x; i < HH; i += blockDim.x) {
        float v = e[i];
        v = v > 0.f ? v : 0.f;
        __nv_bfloat16 h = __float2bfloat16(v);
        g_Xb [(size_t)row*HH + i] = h;
        g_Xlo[(size_t)row*HH + i] = __float2bfloat16(v - __bfloat162float(h));
    }
    if (row < 128){
        int i = row*256 + threadIdx.x;
        if (i == 0) g_bar = 0;
        float v = enc[i];
        g_hf[0][i] = v;
        g_hh16[0][i] = __float2half(v);
    }
}

// ================= GI GEMM: tcgen05 3-term compensated (R10-proven) =================
#define TC_IDESC ((1u<<4)|(1u<<7)|(1u<<10)|(16u<<17)|(8u<<24))   // F32, bf16xbf16, N=128, M=128

__global__ void __launch_bounds__(256) gemm_gi_kernel(
    const __nv_bfloat16* __restrict__ Ah, const __nv_bfloat16* __restrict__ Al,
    const __nv_bfloat16* __restrict__ Bh, const __nv_bfloat16* __restrict__ Bl,
    float* __restrict__ C)
{
    extern __shared__ char dsm[];
    int tid = threadIdx.x, warp = tid >> 5, lane = tid & 31;
    int bm = blockIdx.y * 128, bn = blockIdx.x * 256;

#if TC_OK
    uint32_t sb = smem_u32(dsm);
    if (warp == 0)
        asm volatile("tcgen05.alloc.cta_group::1.sync.aligned.shared::cta.b32 [%0], %1;"
                     :: "r"(sb), "r"(256u) : "memory");
    if (tid == 0){ mbar_init(sb + 8, 1); mbar_init(sb + 16, 1); }
    __syncthreads();
    uint32_t tmem;
    asm volatile("ld.shared.b32 %0, [%1];" : "=r"(tmem) : "r"(sb));

    auto prefetch = [&](int j){
        uint32_t so = sb + 1024 + (uint32_t)(j & 1) * 98304u;
        int kc = j * 64;
        #pragma unroll
        for (int i=0;i<24;i++){
            int cid = tid + i*256;
            if (cid < 2048){
                int mat = cid >> 10, k2 = cid & 1023;
                int r = k2 >> 3, c16 = k2 & 7;
                uint32_t off = (uint32_t)(r*128 + c16*16);
                const __nv_bfloat16* src = (mat ? Al : Ah) + (size_t)(bm + r)*HH + kc + c16*8;
                cp16a(so + (uint32_t)mat*16384u + SWZ128(off), src);
            } else {
                int q = cid - 2048;
                int mat = q >> 11, k2 = q & 2047;
                int r = k2 >> 3, c16 = k2 & 7;
                uint32_t off = (uint32_t)(r*128 + c16*16);
                const __nv_bfloat16* src = (mat ? Bl : Bh) + (size_t)(bn + r)*HH + kc + c16*8;
                cp16a(so + 32768u + (uint32_t)mat*32768u + SWZ128(off), src);
            }
        }
        cp_commit();
    };

    const int NCH = HH / 64;   // 16
    prefetch(0);
    for (int i = 0; i < NCH; ++i){
        int s = i & 1;
        if (i + 1 < NCH){
            if (i >= 1) mbar_wait(sb + 8 + 8*((i-1)&1), (uint32_t)(((i-1)>>1) & 1));
            prefetch(i + 1);
            cp_wait<1>();
        } else cp_wait<0>();
        asm volatile("fence.proxy.async.shared::cta;" ::: "memory");
        __syncthreads();

        if (tid == 0){
            uint32_t so = sb + 1024 + (uint32_t)s * 98304u;
            uint64_t ahd = make_desc(so);
            uint64_t ald = make_desc(so + 16384u);
            uint64_t bh0 = make_desc(so + 32768u);
            uint64_t bh1 = make_desc(so + 49152u);
            uint64_t bl0 = make_desc(so + 65536u);
            uint64_t bl1 = make_desc(so + 81920u);
            #pragma unroll
            for (int ks = 0; ks < 4; ks++){
                uint64_t off = (uint64_t)(ks * 2);
                uint32_t en = (i > 0 || ks > 0) ? 1u : 0u;
                mma_f16_ss(tmem +   0, ahd + off, bh0 + off, TC_IDESC, en);
                mma_f16_ss(tmem +   0, ahd + off, bl0 + off, TC_IDESC, 1u);
                mma_f16_ss(tmem +   0, ald + off, bh0 + off, TC_IDESC, 1u);
                mma_f16_ss(tmem + 128, ahd + off, bh1 + off, TC_IDESC, en);
                mma_f16_ss(tmem + 128, ahd + off, bl1 + off, TC_IDESC, 1u);
                mma_f16_ss(tmem + 128, ald + off, bh1 + off, TC_IDESC, 1u);
            }
            tc_commit(sb + 8 + 8*s);
        }
        __syncthreads();
    }

    mbar_wait(sb + 8,  1);
    mbar_wait(sb + 16, 1);
    TC_FENCE_AFTER();

    {
        int rowgrp = warp & 3, ni = warp >> 2;
        int gr = bm + rowgrp*32 + lane;
        float* op = C + (size_t)gr * H3 + bn + ni*128;
        #pragma unroll
        for (int cc = 0; cc < 4; cc++){
            uint32_t d[32];
            TC_LD_X32(d, tmem + ni*128 + cc*32);
            TC_WAIT_LD();
            #pragma unroll
            for (int q = 0; q < 8; q++){
                float4 v;
                v.x = __uint_as_float(d[q*4+0]);
                v.y = __uint_as_float(d[q*4+1]);
                v.z = __uint_as_float(d[q*4+2]);
                v.w = __uint_as_float(d[q*4+3]);
                *reinterpret_cast<float4*>(op + cc*32 + q*4) = v;
            }
        }
    }

    __syncthreads();
    if (warp == 0){
        asm volatile("tcgen05.relinquish_alloc_permit.cta_group::1.sync.aligned;");
        asm volatile("tcgen05.dealloc.cta_group::1.sync.aligned.b32 %0, %1;" :: "r"(tmem), "r"(256u));
    }
#else
    for (int e = tid; e < 128*256; e += 256){
        int r = e >> 8, c = e & 255;
        float acc = 0.f;
        for (int k = 0; k < HH; k++){
            float ah = __bfloat162float(Ah[(size_t)(bm+r)*HH+k]);
            float al = __bfloat162float(Al[(size_t)(bm+r)*HH+k]);
            float bh = __bfloat162float(Bh[(size_t)(bn+c)*HH+k]);
            float bl = __bfloat162float(Bl[(size_t)(bn+c)*HH+k]);
            acc += ah*bh + ah*bl + al*bh;
        }
        C[(size_t)(bm+r)*H3 + bn + c] = acc;
    }
#endif
}

// ================= output GEMM: tcgen05 256x256 + light fused lsm partials =================
// (change this round: trailing mainloop sync removed; mbar chain self-throttles)
__global__ void __launch_bounds__(512) gemm_out_kernel(
    const __nv_bfloat16* __restrict__ A, const __nv_bfloat16* __restrict__ Bm,
    float* __restrict__ C, const float* __restrict__ bias)
{
    extern __shared__ char dsm[];
    int tid = threadIdx.x, warp = tid >> 5, lane = tid & 31;
    int bm = blockIdx.x * 256, bn = blockIdx.y * 256;

#if TC_OK
    uint32_t sb = smem_u32(dsm);
    if (warp == 0)
        asm volatile("tcgen05.alloc.cta_group::1.sync.aligned.shared::cta.b32 [%0], %1;"
                     :: "r"(sb), "r"(512u) : "memory");
    if (tid == 0){ mbar_init(sb + 8, 1); mbar_init(sb + 16, 1); mbar_init(sb + 24, 1); }
    __syncthreads();
    uint32_t tmem;
    asm volatile("ld.shared.b32 %0, [%1];" : "=r"(tmem) : "r"(sb));

    auto prefetch = [&](int j){
        uint32_t so = sb + 1024 + (uint32_t)(j % 3) * 65536u;
        int kc = j * 64;
        #pragma unroll
        for (int i=0;i<8;i++){
            int cid = tid + i*512;
            if (cid < 2048){
                int r = cid >> 3, c16 = cid & 7;
                int tile = r >> 7, rr = r & 127;
                uint32_t off = (uint32_t)(rr*128 + c16*16);
                cp16a(so + (uint32_t)tile*16384u + SWZ128(off),
                      A + (size_t)(bm + r)*HH + kc + c16*8);
            } else {
                int q = cid - 2048;
                int r = q >> 3, c16 = q & 7;
                uint32_t off = (uint32_t)(r*128 + c16*16);
                cp16a(so + 32768u + SWZ128(off),
                      Bm + (size_t)(bn + r)*HH + kc + c16*8);
            }
        }
        cp_commit();
    };

    const int NCH = HH / 64;   // 16
    prefetch(0);
    prefetch(1);
    for (int i = 0; i < NCH; ++i){
        int s = i % 3;
        if (i + 2 < NCH){
            if (i >= 1) mbar_wait(sb + 8 + 8*((i-1)%3), (uint32_t)(((i-1)/3) & 1));
            prefetch(i + 2);
            cp_wait<2>();
        } else if (i + 1 < NCH) cp_wait<1>();
        else cp_wait<0>();
        asm volatile("fence.proxy.async.shared::cta;" ::: "memory");
        __syncthreads();

        if (tid == 0){
            uint32_t so = sb + 1024 + (uint32_t)s * 65536u;
            uint64_t a0 = make_desc(so);
            uint64_t a1 = make_desc(so + 16384u);
            uint64_t b0 = make_desc(so + 32768u);
            uint64_t b1 = make_desc(so + 49152u);
            #pragma unroll
            for (int ks = 0; ks < 4; ks++){
                uint64_t off = (uint64_t)(ks * 2);
                uint32_t en = (i > 0 || ks > 0) ? 1u : 0u;
                mma_f16_ss(tmem +   0, a0 + off, b0 + off, TC_IDESC, en);
                mma_f16_ss(tmem + 128, a0 + off, b1 + off, TC_IDESC, en);
                mma_f16_ss(tmem + 256, a1 + off, b0 + off, TC_IDESC, en);
                mma_f16_ss(tmem + 384, a1 + off, b1 + off, TC_IDESC, en);
            }
            tc_commit(sb + 8 + 8*s);
        }
        // no trailing sync: non-tid0 threads self-throttle on the mbar commit chain
    }

    mbar_wait(sb + 16, 0);
    mbar_wait(sb + 24, 0);
    mbar_wait(sb + 8,  1);
    TC_FENCE_AFTER();

    // epilogue: stores + per-(row,128col) online (max,sumexp) — light version (R14-proven)
    {
        int rowgrp = warp & 3, tile = warp >> 2;
        int mi = tile >> 1, ni = tile & 1;
        int gr = bm + mi*128 + rowgrp*32 + lane;
        int orow = (gr & 31) * SS + (gr >> 5);
        float* op = C + (size_t)orow * VV + bn + ni*128;
        const float* bp = bias + bn + ni*128;
        float pm = -1e30f, ps = 0.f;
        #pragma unroll
        for (int cc = 0; cc < 4; cc++){
            uint32_t d[32];
            TC_LD_X32(d, tmem + tile*128 + cc*32);
            TC_WAIT_LD();
            float cm = -1e30f;
            #pragma unroll
            for (int q = 0; q < 32; q++)
                cm = fmaxf(cm, __uint_as_float(d[q]) + bp[cc*32 + q]);
            float cs = 0.f;
            #pragma unroll
            for (int q = 0; q < 8; q++){
                float4 v;
                v.x = __uint_as_float(d[q*4+0]) + bp[cc*32 + q*4 + 0];
                v.y = __uint_as_float(d[q*4+1]) + bp[cc*32 + q*4 + 1];
                v.z = __uint_as_float(d[q*4+2]) + bp[cc*32 + q*4 + 2];
                v.w = __uint_as_float(d[q*4+3]) + bp[cc*32 + q*4 + 3];
                cs += expf(v.x - cm) + expf(v.y - cm) + expf(v.z - cm) + expf(v.w - cm);
                *reinterpret_cast<float4*>(op + cc*32 + q*4) = v;
            }
            float nm = fmaxf(pm, cm);
            ps = ps * expf(pm - nm) + cs * expf(cm - nm);
            pm = nm;
        }
        int cb = blockIdx.y*2 + ni;
        g_lsm_m[orow][cb] = pm;
        g_lsm_s[orow][cb] = ps;
    }

    __syncthreads();
    if (warp == 0){
        asm volatile("tcgen05.relinquish_alloc_permit.cta_group::1.sync.aligned;");
        asm volatile("tcgen05.dealloc.cta_group::1.sync.aligned.b32 %0, %1;" :: "r"(tmem), "r"(512u));
    }
#else
    // correct-but-slow canary fallback (also writes partials)
    for (int e = tid; e < 256*256; e += 512){
        int r = e >> 8, c = e & 255;
        float acc = bias[bn + c];
        for (int k = 0; k < HH; k++)
            acc += __bfloat162float(A[(size_t)(bm+r)*HH+k]) *
                   __bfloat162float(Bm[(size_t)(bn+c)*HH+k]);
        int gr = bm + r;
        int orow = (gr & 31) * SS + (gr >> 5);
        C[(size_t)orow * VV + bn + c] = acc;
    }
    __syncthreads();
    if (tid < 256){
        int r = tid;
        int gr = bm + r;
        int orow = (gr & 31) * SS + (gr >> 5);
        for (int half = 0; half < 2; half++){
            float m = -1e30f, s = 0.f;
            for (int c = 0; c < 128; c++){
                float x = C[(size_t)orow * VV + bn + half*128 + c];
                if (x > m){ s = s * expf(m - x) + 1.f; m = x; }
                else s += expf(x - m);
            }
            g_lsm_m[orow][blockIdx.y*2 + half] = m;
            g_lsm_s[orow][blockIdx.y*2 + half] = s;
        }
    }
#endif
}

// ================= persistent GRU: group-local h pipeline =================
// 64 blocks x 768 thr (24 warps). Warp-group g = warps 6g..6g+5 (ksp=g) loads AND
// consumes h K-quarter g exclusively -> named barrier per group replaces the global
// post-load sync. CS has its own region (no Hf alias) -> pre-store sync removed.
// SMEM: Wf [0,99072) | Hf [99072,165120) | CS [165120,189696)
#define JT 16
#define HST 1032
#define GRU_BLOCKS 64
#define GRU_THREADS 768
#define GRU_SMEM 189696

__global__ void __launch_bounds__(GRU_THREADS) gru_persist_kernel(
    const float* __restrict__ bih, const float* __restrict__ bhh)
{
    extern __shared__ char dsm[];
    int tid = threadIdx.x, warp = tid >> 5;
    int j0 = blockIdx.x * JT;

    __half* Wf = (__half*)dsm;
    __half* Hf = (__half*)(dsm + 99072);
    float* CS = (float*)(dsm + 165120);

    // ---- W preload (once): 6144 cp16, 8/thread ----
    #pragma unroll
    for (int i=0;i<8;i++){
        int cid = tid + i*GRU_THREADS;       // 0..6143
        int r = cid >> 7, c16 = cid & 127;
        int wrow = (r >> 4)*HH + j0 + (r & 15);
        cp16(Wf + r*HST + c16*8, g_Whh16 + (size_t)wrow*HH + c16*8);
    }
    cp_commit(); cp_wait<0>(); __syncthreads();

    int g    = warp / 6;         // warp group = K quarter (0..3)
    int tile = warp % 6;
    int mi = tile / 3;           // batch half
    int nj = tile % 3;           // gate
    int ltid = tid - g*192;      // 0..191 within group

    for (int t = 0; t < SS; ++t){
        int cur = t & 1, nxt = cur ^ 1;
        const __half* hsrc = g_hh16[cur];

        // ---- group-local h load: quarter g = 32 rows x 32 chunks = 1024 cp16 ----
        #pragma unroll
        for (int i=0;i<6;i++){
            int cid = ltid + i*192;          // 0..1151
            if (cid < 1024){
                int r = cid >> 5;
                int c = g*256 + (cid & 31)*8;
                cp16(Hf + r*HST + c, hsrc + r*HH + c);
            }
        }
        cp_commit(); cp_wait<0>();
        asm volatile("bar.sync %0, 192;" :: "r"(1 + g) : "memory");

        // ---- sync-free K loop: warp covers K quarter g (16 iters), 2 rotating accs ----
        wmma::fragment<wmma::accumulator,16,16,16,float> acc[2];
        wmma::fill_fragment(acc[0], 0.0f);
        wmma::fill_fragment(acc[1], 0.0f);
        {
            const __half* Ap = Hf + (mi*16)*HST + g*256;
            const __half* Bp = Wf + (nj*16)*HST + g*256;
            #pragma unroll 4
            for (int kk = 0; kk < 16; kk++){
                wmma::fragment<wmma::matrix_a,16,16,16,__half,wmma::row_major> af;
                wmma::fragment<wmma::matrix_b,16,16,16,__half,wmma::col_major> bf;
                wmma::load_matrix_sync(af, Ap + kk*16, HST);
                wmma::load_matrix_sync(bf, Bp + kk*16, HST);
                wmma::mma_sync(acc[kk & 1], af, bf, acc[kk & 1]);
            }
        }
        #pragma unroll
        for (int e = 0; e < acc[0].num_elements; e++) acc[0].x[e] += acc[1].x[e];

        // CS is a private region: store immediately, then one full sync before gate
        wmma::store_matrix_sync(CS + warp*256, acc[0], 16, wmma::mem_row_major);
        __syncthreads();

        // ---- gate update: 512 vals (32 b x 16 j), tid<512 ----
        if (tid < 512){
            int b = tid >> 4, jl = tid & 15;
            int j = j0 + jl;
            int bm2 = b >> 4, b16 = b & 15;
            int o = b16*16 + jl;
            float ghr = 0.f, ghz = 0.f, ghn = 0.f;
            #pragma unroll
            for (int kq = 0; kq < 4; kq++){
                ghr += CS[(kq*6 + bm2*3 + 0)*256 + o];
                ghz += CS[(kq*6 + bm2*3 + 1)*256 + o];
                ghn += CS[(kq*6 + bm2*3 + 2)*256 + o];
            }
            const float* gi = &g_GI[(size_t)(t*BB + b)*H3];
            float gir = gi[j]        + bih[j];
            float giz = gi[HH + j]   + bih[HH + j];
            float gin = gi[2*HH + j] + bih[2*HH + j];
            float r = 1.f/(1.f + expf(-(gir + ghr + bhh[j])));
            float z = 1.f/(1.f + expf(-(giz + ghz + bhh[HH + j])));
            float n = tanhf(gin + r*(ghn + bhh[2*HH + j]));
            float h = (1.f - z)*n + z*g_hf[cur][b*HH + j];
            g_hf[nxt][b*HH + j] = h;
            g_hh16[nxt][b*HH + j] = __float2half(h);
            g_HSb[(size_t)(t*BB + b)*HH + j] = __float2bfloat16(h);
        }

        // ---- grid-wide barrier (64 co-resident blocks) ----
        __threadfence();
        __syncthreads();
        if (tid == 0){
            atomicAdd(&g_bar, 1);
            int target = GRU_BLOCKS * (t + 1);
            while (*(volatile int*)&g_bar < target) { }
        }
        __syncthreads();
    }
}

// ---------------- log_softmax: partial reduce + single subtract pass ----------------
__global__ void lsm_kernel(float* __restrict__ out)
{
    __shared__ float rm[256], rs[256];
    int row = blockIdx.x;
    int t = threadIdx.x;
    float m = -1e30f, s = 0.f;
    if (t < 250){ m = g_lsm_m[row][t]; s = g_lsm_s[row][t]; }
    rm[t] = m; rs[t] = s; __syncthreads();
    for (int st=128; st>0; st>>=1){
        if (t < st){
            float m2 = rm[t+st], s2 = rs[t+st];
            float m1 = rm[t],    s1 = rs[t];
            float M = fmaxf(m1, m2);
            rm[t] = M;
            rs[t] = s1 * expf(m1 - M) + s2 * expf(m2 - M);
        }
        __syncthreads();
    }
    float lse = rm[0] + logf(rs[0]);
    float4* p = (float4*)(out + (size_t)row * VV);
    for (int i = t; i < 8000; i += 256){
        float4 v = p[i];
        v.x -= lse; v.y -= lse; v.z -= lse; v.w -= lse;
        p[i] = v;
    }
}

// ---------------- hT tail ----------------
__global__ void ht_kernel(float* __restrict__ out)
{
    int i = blockIdx.x*blockDim.x + threadIdx.x;
    if (i < BB*HH) out[(size_t)BB*SS*VV + i] = g_hf[0][i];
}

// ---------------- launch ----------------
extern "C" void kernel_launch(void* const* d_in, const int* in_sizes, int n_in,
                              void* d_out, int out_size)
{
    const float* enc_hidden = (const float*)d_in[1];
    const int*   bos        = (const int*)  d_in[2];
    const int*   tgt        = (const int*)  d_in[3];
    const float* emb        = (const float*)d_in[4];
    const float* W_ih       = (const float*)d_in[5];
    const float* W_hh       = (const float*)d_in[6];
    const float* b_ih       = (const float*)d_in[7];
    const float* b_hh       = (const float*)d_in[8];
    const float* W_out      = (const float*)d_in[9];
    const float* b_out      = (const float*)d_in[10];
    float* out = (float*)d_out;

    __nv_bfloat16 *Xb, *Xlo, *Wihb, *Wihlo, *Woutb, *HSb;
    __half *Whh16;
    float *GI;
    cudaGetSymbolAddress((void**)&Xb,    g_Xb);
    cudaGetSymbolAddress((void**)&Xlo,   g_Xlo);
    cudaGetSymbolAddress((void**)&Wihb,  g_Wihb);
    cudaGetSymbolAddress((void**)&Wihlo, g_Wihlo);
    cudaGetSymbolAddress((void**)&Whh16, g_Whh16);
    cudaGetSymbolAddress((void**)&Woutb, g_Woutb);
    cudaGetSymbolAddress((void**)&HSb,   g_HSb);
    cudaGetSymbolAddress((void**)&GI,    g_GI);

    static int smem_set = 0;
    if (!smem_set){
        cudaFuncSetAttribute(gemm_gi_kernel,     cudaFuncAttributeMaxDynamicSharedMemorySize, 197632);
        cudaFuncSetAttribute(gemm_out_kernel,    cudaFuncAttributeMaxDynamicSharedMemorySize, 197632);
        cudaFuncSetAttribute(gru_persist_kernel, cudaFuncAttributeMaxDynamicSharedMemorySize, GRU_SMEM);
        smem_set = 1;
    }

    // launch 0: weight prep (W_ih split + W_hh fp16)
    {
        size_t n4 = (size_t)H3*HH/4;
        wprep_kernel<<<(unsigned)((2*n4+255)/256), 256>>>(
            W_ih, Wihb, Wihlo, W_hh, Whh16, n4);
    }
    // launch 1: embed + h0 init
    embed_init_kernel<<<MM, 256>>>(emb, tgt, bos, enc_hidden);
    // launch 2: GI
    gemm_gi_kernel<<<dim3(H3/256, MM/128), 256, 197632>>>(Xb, Xlo, Wihb, Wihlo, GI);
    // launch 3: GRU  <-- profiled slot
    gru_persist_kernel<<<GRU_BLOCKS, GRU_THREADS, GRU_SMEM>>>(b_ih, b_hh);
    // launch 4: W_out conversion
    {
        size_t n4 = (size_t)VV*HH/4;
        f2b_kernel<<<(unsigned)((n4+255)/256), 256>>>(W_out, Woutb, n4);
    }
    // launch 5: out GEMM (+ fused lsm partials)
    gemm_out_kernel<<<dim3(MM/256, VV/256), 512, 197632>>>(HSb, Woutb, out, b_out);
    // launch 6: lsm (partial reduce + subtract)
    lsm_kernel<<<MM, 256>>>(out);
    // launch 7: hT tail
    ht_kernel<<<128, 256>>>(out);
}

// round 16
// speedup vs baseline: 1.4727x; 1.4727x over previous
#include <cuda_runtime.h>
#include <cuda_bf16.h>
#include <cuda_fp16.h>
#include <mma.h>
#include <cstdint>

using namespace nvcuda;

#define VV 32000
#define HH 1024
#define BB 32
#define SS 64
#define H3 3072
#define MM (SS*BB)   // 2048

#if !defined(__CUDA_ARCH__) || defined(__CUDA_ARCH_FEAT_SM103_ALL)
#define TC_OK 1
#else
#define TC_OK 0
#endif

// ---------------- scratch ----------------
__device__ __half        g_X16[(size_t)MM*HH];     // relu(emb) fp16
__device__ __half        g_Wih16[(size_t)H3*HH];   // W_ih fp16
__device__ __half        g_Whh16[(size_t)H3*HH];   // W_hh fp16
__device__ __nv_bfloat16 g_Woutb[(size_t)VV*HH];
__device__ __nv_bfloat16 g_HSb[(size_t)MM*HH];
__device__ float g_GI[(size_t)MM*H3];
__device__ float g_hf[2][BB*HH];
__device__ __half g_hh16[2][BB*HH];
__device__ float g_lsm_m[MM][256];   // per-(row, 128-col block) max (250 used)
__device__ float g_lsm_s[MM][256];   // per-(row, 128-col block) sumexp
__device__ int g_bar;

// ---------------- cp.async helpers ----------------
__device__ __forceinline__ uint32_t smem_u32(const void* p){
    return (uint32_t)__cvta_generic_to_shared(p);
}
__device__ __forceinline__ void cp16(void* dst, const void* src){
    asm volatile("cp.async.cg.shared.global [%0], [%1], 16;" :: "r"(smem_u32(dst)), "l"(src));
}
__device__ __forceinline__ void cp16a(uint32_t dst, const void* src){
    asm volatile("cp.async.cg.shared.global [%0], [%1], 16;" :: "r"(dst), "l"(src));
}
__device__ __forceinline__ void cp_commit(){ asm volatile("cp.async.commit_group;"); }
template<int N> __device__ __forceinline__ void cp_wait(){ asm volatile("cp.async.wait_group %0;" :: "n"(N)); }

#define SWZ128(off) ((off) ^ (((off) >> 3) & 0x70))

#if TC_OK
// ---------------- tcgen05 helpers ----------------
static __device__ __forceinline__ uint64_t make_desc(uint32_t addr){
    const uint64_t base = (2ULL<<61) | (1ULL<<46) | (64ULL<<32) | (1ULL<<16); // SW128, v1, SBO=64, LBO=1
    return base | (uint64_t)((addr >> 4) & 0x3FFF);
}
__device__ __forceinline__ void mma_f16_ss(uint32_t d, uint64_t ad, uint64_t bd, uint32_t idesc, uint32_t en){
    asm volatile(
        "{\n\t.reg .pred p;\n\t"
        "setp.ne.u32 p, %5, 0;\n\t"
        "tcgen05.mma.cta_group::1.kind::f16 [%0], %1, %2, %3, {%4, %4, %4, %4}, p;\n\t}"
        :: "r"(d), "l"(ad), "l"(bd), "r"(idesc), "r"(0u), "r"(en) : "memory");
}
__device__ __forceinline__ void tc_commit(uint32_t mbar){
    asm volatile("tcgen05.commit.cta_group::1.mbarrier::arrive::one.shared::cluster.b64 [%0];" :: "r"(mbar) : "memory");
}
__device__ __forceinline__ void mbar_init(uint32_t mbar, uint32_t cnt){
    asm volatile("mbarrier.init.shared.b64 [%0], %1;" :: "r"(mbar), "r"(cnt) : "memory");
}
__device__ __forceinline__ void mbar_wait(uint32_t mbar, uint32_t parity){
    asm volatile(
        "{\n\t.reg .pred P1;\n\t"
        "W_%=:\n\t"
        "mbarrier.try_wait.parity.acquire.cta.shared::cta.b64 P1, [%0], %1, 0x989680;\n\t"
        "@!P1 bra.uni W_%=;\n\t}"
        :: "r"(mbar), "r"(parity) : "memory");
}
#define TC_LD_X32(r, a) \
    asm volatile( \
        "tcgen05.ld.sync.aligned.32x32b.x32.b32 " \
        "{%0, %1, %2, %3, %4, %5, %6, %7, " \
        " %8, %9, %10, %11, %12, %13, %14, %15, " \
        " %16, %17, %18, %19, %20, %21, %22, %23, " \
        " %24, %25, %26, %27, %28, %29, %30, %31}, [%32];" \
        : "=r"((r)[0]),  "=r"((r)[1]),  "=r"((r)[2]),  "=r"((r)[3]), \
          "=r"((r)[4]),  "=r"((r)[5]),  "=r"((r)[6]),  "=r"((r)[7]), \
          "=r"((r)[8]),  "=r"((r)[9]),  "=r"((r)[10]), "=r"((r)[11]), \
          "=r"((r)[12]), "=r"((r)[13]), "=r"((r)[14]), "=r"((r)[15]), \
          "=r"((r)[16]), "=r"((r)[17]), "=r"((r)[18]), "=r"((r)[19]), \
          "=r"((r)[20]), "=r"((r)[21]), "=r"((r)[22]), "=r"((r)[23]), \
          "=r"((r)[24]), "=r"((r)[25]), "=r"((r)[26]), "=r"((r)[27]), \
          "=r"((r)[28]), "=r"((r)[29]), "=r"((r)[30]), "=r"((r)[31]) \
        : "r"(a))
#define TC_WAIT_LD()  asm volatile("tcgen05.wait::ld.sync.aligned;" ::: "memory")
#define TC_FENCE_AFTER() asm volatile("tcgen05.fence::after_thread_sync;" ::: "memory")
#endif // TC_OK

// idesc: F32 accum; fp16 x fp16 (atype=btype=0); N=128, M=128
#define TC_IDESC_BF16 ((1u<<4)|(1u<<7)|(1u<<10)|(16u<<17)|(8u<<24))
#define TC_IDESC_F16  ((1u<<4)|(16u<<17)|(8u<<24))

// ---------------- fp32 -> bf16 ----------------
__global__ void f2b_kernel(const float* __restrict__ in, __nv_bfloat16* __restrict__ out, size_t n4)
{
    size_t i = (size_t)blockIdx.x * blockDim.x + threadIdx.x;
    if (i >= n4) return;
    float4 v = reinterpret_cast<const float4*>(in)[i];
    reinterpret_cast<__nv_bfloat162*>(out)[2*i]   = __floats2bfloat162_rn(v.x, v.y);
    reinterpret_cast<__nv_bfloat162*>(out)[2*i+1] = __floats2bfloat162_rn(v.z, v.w);
}

// ---------------- weight prep: W_ih -> fp16, W_hh -> fp16 (one launch) ----------------
__global__ void wprep_kernel(const float* __restrict__ wih, __half* __restrict__ wih16,
                             const float* __restrict__ whh, __half* __restrict__ whh16,
                             size_t n4each)
{
    size_t i = (size_t)blockIdx.x * blockDim.x + threadIdx.x;
    if (i >= 2*n4each) return;
    const float* in; __half* out;
    if (i >= n4each){ i -= n4each; in = whh; out = whh16; }
    else            {              in = wih; out = wih16; }
    float4 v = reinterpret_cast<const float4*>(in)[i];
    reinterpret_cast<__half2*>(out)[2*i]   = __floats2half2_rn(v.x, v.y);
    reinterpret_cast<__half2*>(out)[2*i+1] = __floats2half2_rn(v.z, v.w);
}

// ---------------- embedding+relu->fp16 + h0 init ----------------
__global__ void embed_init_kernel(const float* __restrict__ emb, const int* __restrict__ tgt,
                                  const int* __restrict__ bos, const float* __restrict__ enc)
{
    int row = blockIdx.x;
    int t = row >> 5, b = row & 31;
    int tok = (t == 0) ? bos[0] : tgt[b*SS + t - 1];
    const float* e = &emb[(size_t)tok * HH];
    for (int i = threadIdx.x; i < HH; i += blockDim.x) {
        float v = e[i];
        v = v > 0.f ? v : 0.f;
        g_X16[(size_t)row*HH + i] = __float2half(v);
    }
    if (row < 128){
        int i = row*256 + threadIdx.x;
        if (i == 0) g_bar = 0;
        float v = enc[i];
        g_hf[0][i] = v;
        g_hh16[0][i] = __float2half(v);
    }
}

// ================= GI GEMM: tcgen05 fp16 single-term, 256x256 tile =================
// GI[2048,3072] = X16 @ Wih16^T. Grid (MM/256=8, H3/256=12); x-fastest shares B in L2.
__global__ void __launch_bounds__(512) gemm_gi_kernel(
    const __half* __restrict__ A, const __half* __restrict__ Bm,
    float* __restrict__ C)
{
    extern __shared__ char dsm[];
    int tid = threadIdx.x, warp = tid >> 5, lane = tid & 31;
    int bm = blockIdx.x * 256, bn = blockIdx.y * 256;

#if TC_OK
    uint32_t sb = smem_u32(dsm);
    if (warp == 0)
        asm volatile("tcgen05.alloc.cta_group::1.sync.aligned.shared::cta.b32 [%0], %1;"
                     :: "r"(sb), "r"(512u) : "memory");
    if (tid == 0){ mbar_init(sb + 8, 1); mbar_init(sb + 16, 1); mbar_init(sb + 24, 1); }
    __syncthreads();
    uint32_t tmem;
    asm volatile("ld.shared.b32 %0, [%1];" : "=r"(tmem) : "r"(sb));

    auto prefetch = [&](int j){
        uint32_t so = sb + 1024 + (uint32_t)(j % 3) * 65536u;
        int kc = j * 64;
        #pragma unroll
        for (int i=0;i<8;i++){
            int cid = tid + i*512;
            if (cid < 2048){
                int r = cid >> 3, c16 = cid & 7;
                int tile = r >> 7, rr = r & 127;
                uint32_t off = (uint32_t)(rr*128 + c16*16);
                cp16a(so + (uint32_t)tile*16384u + SWZ128(off),
                      A + (size_t)(bm + r)*HH + kc + c16*8);
            } else {
                int q = cid - 2048;
                int r = q >> 3, c16 = q & 7;
                uint32_t off = (uint32_t)(r*128 + c16*16);
                cp16a(so + 32768u + SWZ128(off),
                      Bm + (size_t)(bn + r)*HH + kc + c16*8);
            }
        }
        cp_commit();
    };

    const int NCH = HH / 64;   // 16
    prefetch(0);
    prefetch(1);
    for (int i = 0; i < NCH; ++i){
        int s = i % 3;
        if (i + 2 < NCH){
            if (i >= 1) mbar_wait(sb + 8 + 8*((i-1)%3), (uint32_t)(((i-1)/3) & 1));
            prefetch(i + 2);
            cp_wait<2>();
        } else if (i + 1 < NCH) cp_wait<1>();
        else cp_wait<0>();
        asm volatile("fence.proxy.async.shared::cta;" ::: "memory");
        __syncthreads();

        if (tid == 0){
            uint32_t so = sb + 1024 + (uint32_t)s * 65536u;
            uint64_t a0 = make_desc(so);
            uint64_t a1 = make_desc(so + 16384u);
            uint64_t b0 = make_desc(so + 32768u);
            uint64_t b1 = make_desc(so + 49152u);
            #pragma unroll
            for (int ks = 0; ks < 4; ks++){
                uint64_t off = (uint64_t)(ks * 2);
                uint32_t en = (i > 0 || ks > 0) ? 1u : 0u;
                mma_f16_ss(tmem +   0, a0 + off, b0 + off, TC_IDESC_F16, en);
                mma_f16_ss(tmem + 128, a0 + off, b1 + off, TC_IDESC_F16, en);
                mma_f16_ss(tmem + 256, a1 + off, b0 + off, TC_IDESC_F16, en);
                mma_f16_ss(tmem + 384, a1 + off, b1 + off, TC_IDESC_F16, en);
            }
            tc_commit(sb + 8 + 8*s);
        }
        __syncthreads();   // trailing sync: R15-proven necessary
    }

    mbar_wait(sb + 16, 0);
    mbar_wait(sb + 24, 0);
    mbar_wait(sb + 8,  1);
    TC_FENCE_AFTER();

    // epilogue: plain stores to GI (no bias/remap)
    {
        int rowgrp = warp & 3, tile = warp >> 2;
        int mi = tile >> 1, ni = tile & 1;
        int gr = bm + mi*128 + rowgrp*32 + lane;
        float* op = C + (size_t)gr * H3 + bn + ni*128;
        #pragma unroll
        for (int cc = 0; cc < 4; cc++){
            uint32_t d[32];
            TC_LD_X32(d, tmem + tile*128 + cc*32);
            TC_WAIT_LD();
            #pragma unroll
            for (int q = 0; q < 8; q++){
                float4 v;
                v.x = __uint_as_float(d[q*4+0]);
                v.y = __uint_as_float(d[q*4+1]);
                v.z = __uint_as_float(d[q*4+2]);
                v.w = __uint_as_float(d[q*4+3]);
                *reinterpret_cast<float4*>(op + cc*32 + q*4) = v;
            }
        }
    }

    __syncthreads();
    if (warp == 0){
        asm volatile("tcgen05.relinquish_alloc_permit.cta_group::1.sync.aligned;");
        asm volatile("tcgen05.dealloc.cta_group::1.sync.aligned.b32 %0, %1;" :: "r"(tmem), "r"(512u));
    }
#else
    for (int e = tid; e < 256*256; e += 512){
        int r = e >> 8, c = e & 255;
        float acc = 0.f;
        for (int k = 0; k < HH; k++)
            acc += __half2float(A[(size_t)(bm+r)*HH+k]) *
                   __half2float(Bm[(size_t)(bn+c)*HH+k]);
        C[(size_t)(bm+r)*H3 + bn + c] = acc;
    }
#endif
}

// ================= output GEMM: tcgen05 256x256 + light fused lsm partials (R14-proven) =================
__global__ void __launch_bounds__(512) gemm_out_kernel(
    const __nv_bfloat16* __restrict__ A, const __nv_bfloat16* __restrict__ Bm,
    float* __restrict__ C, const float* __restrict__ bias)
{
    extern __shared__ char dsm[];
    int tid = threadIdx.x, warp = tid >> 5, lane = tid & 31;
    int bm = blockIdx.x * 256, bn = blockIdx.y * 256;

#if TC_OK
    uint32_t sb = smem_u32(dsm);
    if (warp == 0)
        asm volatile("tcgen05.alloc.cta_group::1.sync.aligned.shared::cta.b32 [%0], %1;"
                     :: "r"(sb), "r"(512u) : "memory");
    if (tid == 0){ mbar_init(sb + 8, 1); mbar_init(sb + 16, 1); mbar_init(sb + 24, 1); }
    __syncthreads();
    uint32_t tmem;
    asm volatile("ld.shared.b32 %0, [%1];" : "=r"(tmem) : "r"(sb));

    auto prefetch = [&](int j){
        uint32_t so = sb + 1024 + (uint32_t)(j % 3) * 65536u;
        int kc = j * 64;
        #pragma unroll
        for (int i=0;i<8;i++){
            int cid = tid + i*512;
            if (cid < 2048){
                int r = cid >> 3, c16 = cid & 7;
                int tile = r >> 7, rr = r & 127;
                uint32_t off = (uint32_t)(rr*128 + c16*16);
                cp16a(so + (uint32_t)tile*16384u + SWZ128(off),
                      A + (size_t)(bm + r)*HH + kc + c16*8);
            } else {
                int q = cid - 2048;
                int r = q >> 3, c16 = q & 7;
                uint32_t off = (uint32_t)(r*128 + c16*16);
                cp16a(so + 32768u + SWZ128(off),
                      Bm + (size_t)(bn + r)*HH + kc + c16*8);
            }
        }
        cp_commit();
    };

    const int NCH = HH / 64;   // 16
    prefetch(0);
    prefetch(1);
    for (int i = 0; i < NCH; ++i){
        int s = i % 3;
        if (i + 2 < NCH){
            if (i >= 1) mbar_wait(sb + 8 + 8*((i-1)%3), (uint32_t)(((i-1)/3) & 1));
            prefetch(i + 2);
            cp_wait<2>();
        } else if (i + 1 < NCH) cp_wait<1>();
        else cp_wait<0>();
        asm volatile("fence.proxy.async.shared::cta;" ::: "memory");
        __syncthreads();

        if (tid == 0){
            uint32_t so = sb + 1024 + (uint32_t)s * 65536u;
            uint64_t a0 = make_desc(so);
            uint64_t a1 = make_desc(so + 16384u);
            uint64_t b0 = make_desc(so + 32768u);
            uint64_t b1 = make_desc(so + 49152u);
            #pragma unroll
            for (int ks = 0; ks < 4; ks++){
                uint64_t off = (uint64_t)(ks * 2);
                uint32_t en = (i > 0 || ks > 0) ? 1u : 0u;
                mma_f16_ss(tmem +   0, a0 + off, b0 + off, TC_IDESC_BF16, en);
                mma_f16_ss(tmem + 128, a0 + off, b1 + off, TC_IDESC_BF16, en);
                mma_f16_ss(tmem + 256, a1 + off, b0 + off, TC_IDESC_BF16, en);
                mma_f16_ss(tmem + 384, a1 + off, b1 + off, TC_IDESC_BF16, en);
            }
            tc_commit(sb + 8 + 8*s);
        }
        __syncthreads();   // trailing sync: R15-proven necessary
    }

    mbar_wait(sb + 16, 0);
    mbar_wait(sb + 24, 0);
    mbar_wait(sb + 8,  1);
    TC_FENCE_AFTER();

    // epilogue: stores + per-(row,128col) online (max,sumexp) — light version (R14-proven)
    {
        int rowgrp = warp & 3, tile = warp >> 2;
        int mi = tile >> 1, ni = tile & 1;
        int gr = bm + mi*128 + rowgrp*32 + lane;
        int orow = (gr & 31) * SS + (gr >> 5);
        float* op = C + (size_t)orow * VV + bn + ni*128;
        const float* bp = bias + bn + ni*128;
        float pm = -1e30f, ps = 0.f;
        #pragma unroll
        for (int cc = 0; cc < 4; cc++){
            uint32_t d[32];
            TC_LD_X32(d, tmem + tile*128 + cc*32);
            TC_WAIT_LD();
            float cm = -1e30f;
            #pragma unroll
            for (int q = 0; q < 32; q++)
                cm = fmaxf(cm, __uint_as_float(d[q]) + bp[cc*32 + q]);
            float cs = 0.f;
            #pragma unroll
            for (int q = 0; q < 8; q++){
                float4 v;
                v.x = __uint_as_float(d[q*4+0]) + bp[cc*32 + q*4 + 0];
                v.y = __uint_as_float(d[q*4+1]) + bp[cc*32 + q*4 + 1];
                v.z = __uint_as_float(d[q*4+2]) + bp[cc*32 + q*4 + 2];
                v.w = __uint_as_float(d[q*4+3]) + bp[cc*32 + q*4 + 3];
                cs += expf(v.x - cm) + expf(v.y - cm) + expf(v.z - cm) + expf(v.w - cm);
                *reinterpret_cast<float4*>(op + cc*32 + q*4) = v;
            }
            float nm = fmaxf(pm, cm);
            ps = ps * expf(pm - nm) + cs * expf(cm - nm);
            pm = nm;
        }
        int cb = blockIdx.y*2 + ni;
        g_lsm_m[orow][cb] = pm;
        g_lsm_s[orow][cb] = ps;
    }

    __syncthreads();
    if (warp == 0){
        asm volatile("tcgen05.relinquish_alloc_permit.cta_group::1.sync.aligned;");
        asm volatile("tcgen05.dealloc.cta_group::1.sync.aligned.b32 %0, %1;" :: "r"(tmem), "r"(512u));
    }
#else
    for (int e = tid; e < 256*256; e += 512){
        int r = e >> 8, c = e & 255;
        float acc = bias[bn + c];
        for (int k = 0; k < HH; k++)
            acc += __bfloat162float(A[(size_t)(bm+r)*HH+k]) *
                   __bfloat162float(Bm[(size_t)(bn+c)*HH+k]);
        int gr = bm + r;
        int orow = (gr & 31) * SS + (gr >> 5);
        C[(size_t)orow * VV + bn + c] = acc;
    }
    __syncthreads();
    if (tid < 256){
        int r = tid;
        int gr = bm + r;
        int orow = (gr & 31) * SS + (gr >> 5);
        for (int half = 0; half < 2; half++){
            float m = -1e30f, s = 0.f;
            for (int c = 0; c < 128; c++){
                float x = C[(size_t)orow * VV + bn + half*128 + c];
                if (x > m){ s = s * expf(m - x) + 1.f; m = x; }
                else s += expf(x - m);
            }
            g_lsm_m[orow][blockIdx.y*2 + half] = m;
            g_lsm_s[orow][blockIdx.y*2 + half] = s;
        }
    }
#endif
}

// ================= persistent GRU: fp16 single-term, 64 blocks x 768 thr (R14-proven) =================
#define JT 16
#define HST 1032
#define GRU_BLOCKS 64
#define GRU_THREADS 768
#define GRU_SMEM 165120

__global__ void __launch_bounds__(GRU_THREADS) gru_persist_kernel(
    const float* __restrict__ bih, const float* __restrict__ bhh)
{
    extern __shared__ char dsm[];
    int tid = threadIdx.x, warp = tid >> 5;
    int j0 = blockIdx.x * JT;

    __half* Wf = (__half*)dsm;
    __half* Hf = (__half*)(dsm + 99072);
    float* CS = (float*)(dsm + 99072);   // aliases Hf after compute

    // ---- W preload (once): 6144 cp16, 8/thread ----
    #pragma unroll
    for (int i=0;i<8;i++){
        int cid = tid + i*GRU_THREADS;
        int r = cid >> 7, c16 = cid & 127;
        int wrow = (r >> 4)*HH + j0 + (r & 15);
        cp16(Wf + r*HST + c16*8, g_Whh16 + (size_t)wrow*HH + c16*8);
    }
    cp_commit(); cp_wait<0>(); __syncthreads();

    int ksp  = warp / 6;         // 0..3 (K split quarters)
    int tile = warp % 6;
    int mi = tile / 3;           // batch half
    int nj = tile % 3;           // gate

    for (int t = 0; t < SS; ++t){
        int cur = t & 1, nxt = cur ^ 1;
        const __half* hsrc = g_hh16[cur];

        // ---- load h: 4096 cp16 over 768 threads ----
        #pragma unroll
        for (int i=0;i<6;i++){
            int cid = tid + i*GRU_THREADS;
            if (cid < 4096){
                int r = cid >> 7, c16 = cid & 127;
                cp16(Hf + r*HST + c16*8, hsrc + r*HH + c16*8);
            }
        }
        cp_commit(); cp_wait<0>();
        __syncthreads();

        // ---- sync-free K loop: each warp K=256 (16 iters), 2 rotating accs ----
        wmma::fragment<wmma::accumulator,16,16,16,float> acc[2];
        wmma::fill_fragment(acc[0], 0.0f);
        wmma::fill_fragment(acc[1], 0.0f);
        {
            const __half* Ap = Hf + (mi*16)*HST + ksp*256;
            const __half* Bp = Wf + (nj*16)*HST + ksp*256;
            #pragma unroll 4
            for (int kk = 0; kk < 16; kk++){
                wmma::fragment<wmma::matrix_a,16,16,16,__half,wmma::row_major> af;
                wmma::fragment<wmma::matrix_b,16,16,16,__half,wmma::col_major> bf;
                wmma::load_matrix_sync(af, Ap + kk*16, HST);
                wmma::load_matrix_sync(bf, Bp + kk*16, HST);
                wmma::mma_sync(acc[kk & 1], af, bf, acc[kk & 1]);
            }
        }
        #pragma unroll
        for (int e = 0; e < acc[0].num_elements; e++) acc[0].x[e] += acc[1].x[e];

        __syncthreads();   // all warps done reading Hf before CS aliases it
        wmma::store_matrix_sync(CS + warp*256, acc[0], 16, wmma::mem_row_major);
        __syncthreads();

        // ---- gate update: 512 vals (32 b x 16 j), tid<512 ----
        if (tid < 512){
            int b = tid >> 4, jl = tid & 15;
            int j = j0 + jl;
            int bm2 = b >> 4, b16 = b & 15;
            int o = b16*16 + jl;
            float ghr = 0.f, ghz = 0.f, ghn = 0.f;
            #pragma unroll
            for (int kq = 0; kq < 4; kq++){
                ghr += CS[(kq*6 + bm2*3 + 0)*256 + o];
                ghz += CS[(kq*6 + bm2*3 + 1)*256 + o];
                ghn += CS[(kq*6 + bm2*3 + 2)*256 + o];
            }
            const float* gi = &g_GI[(size_t)(t*BB + b)*H3];
            float gir = gi[j]        + bih[j];
            float giz = gi[HH + j]   + bih[HH + j];
            float gin = gi[2*HH + j] + bih[2*HH + j];
            float r = 1.f/(1.f + expf(-(gir + ghr + bhh[j])));
            float z = 1.f/(1.f + expf(-(giz + ghz + bhh[HH + j])));
            float n = tanhf(gin + r*(ghn + bhh[2*HH + j]));
            float h = (1.f - z)*n + z*g_hf[cur][b*HH + j];
            g_hf[nxt][b*HH + j] = h;
            g_hh16[nxt][b*HH + j] = __float2half(h);
            g_HSb[(size_t)(t*BB + b)*HH + j] = __float2bfloat16(h);
        }

        // ---- grid-wide barrier (64 co-resident blocks) ----
        __threadfence();
        __syncthreads();
        if (tid == 0){
            atomicAdd(&g_bar, 1);
            int target = GRU_BLOCKS * (t + 1);
            while (*(volatile int*)&g_bar < target) { }
        }
        __syncthreads();
    }
}

// ---------------- log_softmax: partial reduce + single subtract pass ----------------
__global__ void lsm_kernel(float* __restrict__ out)
{
    __shared__ float rm[256], rs[256];
    int row = blockIdx.x;
    int t = threadIdx.x;
    float m = -1e30f, s = 0.f;
    if (t < 250){ m = g_lsm_m[row][t]; s = g_lsm_s[row][t]; }
    rm[t] = m; rs[t] = s; __syncthreads();
    for (int st=128; st>0; st>>=1){
        if (t < st){
            float m2 = rm[t+st], s2 = rs[t+st];
            float m1 = rm[t],    s1 = rs[t];
            float M = fmaxf(m1, m2);
            rm[t] = M;
            rs[t] = s1 * expf(m1 - M) + s2 * expf(m2 - M);
        }
        __syncthreads();
    }
    float lse = rm[0] + logf(rs[0]);
    float4* p = (float4*)(out + (size_t)row * VV);
    for (int i = t; i < 8000; i += 256){
        float4 v = p[i];
        v.x -= lse; v.y -= lse; v.z -= lse; v.w -= lse;
        p[i] = v;
    }
}

// ---------------- hT tail ----------------
__global__ void ht_kernel(float* __restrict__ out)
{
    int i = blockIdx.x*blockDim.x + threadIdx.x;
    if (i < BB*HH) out[(size_t)BB*SS*VV + i] = g_hf[0][i];
}

// ---------------- launch ----------------
extern "C" void kernel_launch(void* const* d_in, const int* in_sizes, int n_in,
                              void* d_out, int out_size)
{
    const float* enc_hidden = (const float*)d_in[1];
    const int*   bos        = (const int*)  d_in[2];
    const int*   tgt        = (const int*)  d_in[3];
    const float* emb        = (const float*)d_in[4];
    const float* W_ih       = (const float*)d_in[5];
    const float* W_hh       = (const float*)d_in[6];
    const float* b_ih       = (const float*)d_in[7];
    const float* b_hh       = (const float*)d_in[8];
    const float* W_out      = (const float*)d_in[9];
    const float* b_out      = (const float*)d_in[10];
    float* out = (float*)d_out;

    __half *X16, *Wih16, *Whh16;
    __nv_bfloat16 *Woutb, *HSb;
    float *GI;
    cudaGetSymbolAddress((void**)&X16,   g_X16);
    cudaGetSymbolAddress((void**)&Wih16, g_Wih16);
    cudaGetSymbolAddress((void**)&Whh16, g_Whh16);
    cudaGetSymbolAddress((void**)&Woutb, g_Woutb);
    cudaGetSymbolAddress((void**)&HSb,   g_HSb);
    cudaGetSymbolAddress((void**)&GI,    g_GI);

    static int smem_set = 0;
    if (!smem_set){
        cudaFuncSetAttribute(gemm_gi_kernel,     cudaFuncAttributeMaxDynamicSharedMemorySize, 197632);
        cudaFuncSetAttribute(gemm_out_kernel,    cudaFuncAttributeMaxDynamicSharedMemorySize, 197632);
        cudaFuncSetAttribute(gru_persist_kernel, cudaFuncAttributeMaxDynamicSharedMemorySize, GRU_SMEM);
        smem_set = 1;
    }

    // launch 0: weight prep (W_ih + W_hh -> fp16)
    {
        size_t n4 = (size_t)H3*HH/4;
        wprep_kernel<<<(unsigned)((2*n4+255)/256), 256>>>(W_ih, Wih16, W_hh, Whh16, n4);
    }
    // launch 1: embed + h0 init
    embed_init_kernel<<<MM, 256>>>(emb, tgt, bos, enc_hidden);
    // launch 2: GI (fp16 single-term tcgen05)
    gemm_gi_kernel<<<dim3(MM/256, H3/256), 512, 197632>>>(X16, Wih16, GI);
    // launch 3: GRU  <-- profiled slot
    gru_persist_kernel<<<GRU_BLOCKS, GRU_THREADS, GRU_SMEM>>>(b_ih, b_hh);
    // launch 4: W_out conversion
    {
        size_t n4 = (size_t)VV*HH/4;
        f2b_kernel<<<(unsigned)((n4+255)/256), 256>>>(W_out, Woutb, n4);
    }
    // launch 5: out GEMM (+ fused lsm partials)
    gemm_out_kernel<<<dim3(MM/256, VV/256), 512, 197632>>>(HSb, Woutb, out, b_out);
    // launch 6: lsm (partial reduce + subtract)
    lsm_kernel<<<MM, 256>>>(out);
    // launch 7: hT tail
    ht_kernel<<<128, 256>>>(out);
}